// round 1
// baseline (speedup 1.0000x reference)
#include <cuda_runtime.h>
#include <math.h>

#define DIM_  1024
#define DIN_  1536
#define B_    4
#define L_    4096
#define M_    (B_ * L_)          // 16384
#define NCHUNK_ 32
#define CHUNK_  (L_ / NCHUNK_)   // 128

// ---------------- static scratch (no allocations allowed) ----------------
__device__ float g_xz[(size_t)M_ * 2 * DIN_];    // in_proj output: [M, 3072] (x_inner | z)
__device__ float g_xconv[(size_t)M_ * DIN_];     // silu(conv(x_inner))
__device__ float g_dt[(size_t)M_ * DIN_];        // softplus(x_conv @ dt_w^T + dt_b)
__device__ float g_s[(size_t)M_ * DIN_];         // x_conv * dt * A_exp
__device__ float g_ae[(size_t)M_ * DIN_];        // A_exp
__device__ float g_y[(size_t)M_ * DIN_];         // final y before out_proj
__device__ float g_csum[B_ * NCHUNK_ * DIN_];    // per-chunk sums
__device__ float g_cpre[B_ * NCHUNK_ * DIN_];    // exclusive chunk prefixes

__device__ __forceinline__ float softplus_f(float v) {
    return v > 20.f ? v : log1pf(expf(v));
}
__device__ __forceinline__ float silu_f(float v) {
    return v / (1.f + expf(-v));
}

// ---------------- SGEMM: C[m,n] = sum_k A[m,k] * B[n,k]  (both K-contiguous) --
// 128x128 block tile, BK=8, 8x8 per thread, 256 threads.
// MODE 0: plain store.  MODE 1: softplus(acc + bias[n]).
template <int MODE>
__global__ void __launch_bounds__(256)
sgemm_nt(const float* __restrict__ A, const float* __restrict__ B,
         float* __restrict__ C, const float* __restrict__ bias,
         int M, int N, int K)
{
    __shared__ float As[8][128];
    __shared__ float Bs[8][128];
    const int tid  = threadIdx.x;
    const int tx   = tid & 15;        // N-direction thread coord
    const int ty   = tid >> 4;        // M-direction thread coord
    const int lrow = tid >> 1;        // 0..127 (tile row for loading)
    const int lcol = (tid & 1) << 2;  // 0 or 4 (k offset for float4 load)

    const float* Ag = A + ((size_t)blockIdx.y * 128 + lrow) * K + lcol;
    const float* Bg = B + ((size_t)blockIdx.x * 128 + lrow) * K + lcol;

    float acc[8][8];
#pragma unroll
    for (int i = 0; i < 8; i++)
#pragma unroll
        for (int j = 0; j < 8; j++) acc[i][j] = 0.f;

    for (int k0 = 0; k0 < K; k0 += 8) {
        float4 av = *(const float4*)(Ag + k0);
        float4 bv = *(const float4*)(Bg + k0);
        __syncthreads();  // previous tile's compute done before overwrite
        As[lcol + 0][lrow] = av.x; As[lcol + 1][lrow] = av.y;
        As[lcol + 2][lrow] = av.z; As[lcol + 3][lrow] = av.w;
        Bs[lcol + 0][lrow] = bv.x; Bs[lcol + 1][lrow] = bv.y;
        Bs[lcol + 2][lrow] = bv.z; Bs[lcol + 3][lrow] = bv.w;
        __syncthreads();
#pragma unroll
        for (int kk = 0; kk < 8; kk++) {
            float4 a0 = *(const float4*)&As[kk][ty * 8];
            float4 a1 = *(const float4*)&As[kk][ty * 8 + 4];
            float4 b0 = *(const float4*)&Bs[kk][tx * 8];
            float4 b1 = *(const float4*)&Bs[kk][tx * 8 + 4];
            float ar[8] = {a0.x, a0.y, a0.z, a0.w, a1.x, a1.y, a1.z, a1.w};
            float br[8] = {b0.x, b0.y, b0.z, b0.w, b1.x, b1.y, b1.z, b1.w};
#pragma unroll
            for (int i = 0; i < 8; i++)
#pragma unroll
                for (int j = 0; j < 8; j++)
                    acc[i][j] = fmaf(ar[i], br[j], acc[i][j]);
        }
    }

    const size_t row0 = (size_t)blockIdx.y * 128 + (size_t)ty * 8;
    const int    col0 = blockIdx.x * 128 + tx * 8;
#pragma unroll
    for (int i = 0; i < 8; i++) {
#pragma unroll
        for (int j = 0; j < 8; j++) {
            float v = acc[i][j];
            if (MODE == 1) v = softplus_f(v + bias[col0 + j]);
            C[(row0 + i) * N + col0 + j] = v;
        }
    }
}

// ---------------- depthwise conv3 (pad=1) + bias + SiLU -----------------------
__global__ void __launch_bounds__(256)
conv_silu_kernel(const float* __restrict__ cw, const float* __restrict__ cb)
{
    int idx = blockIdx.x * blockDim.x + threadIdx.x;  // over M_*DIN_
    int c  = idx % DIN_;
    int bl = idx / DIN_;
    int l  = bl % L_;
    const float* base = g_xz + (size_t)bl * (2 * DIN_) + c;
    float x0 = base[0];
    float xm = (l > 0)      ? base[-(2 * DIN_)] : 0.f;
    float xp = (l < L_ - 1) ? base[ (2 * DIN_)] : 0.f;
    float w0 = __ldg(&cw[c * 3 + 0]);
    float w1 = __ldg(&cw[c * 3 + 1]);
    float w2 = __ldg(&cw[c * 3 + 2]);
    float v = fmaf(w0, xm, fmaf(w1, x0, fmaf(w2, xp, __ldg(&cb[c]))));
    g_xconv[idx] = silu_f(v);
}

// ---------------- scan phase 1: compute s, ae, per-chunk sums -----------------
__global__ void __launch_bounds__(256)
scan_phase1(const float* __restrict__ Aw)
{
    const int ct = blockIdx.y % (DIN_ / 256);
    const int b  = blockIdx.y / (DIN_ / 256);
    const int ch = blockIdx.x;
    const int c  = ct * 256 + threadIdx.x;
    const float Ac = __ldg(&Aw[c]);
    size_t base = ((size_t)b * L_ + (size_t)ch * CHUNK_) * DIN_ + c;
    float sum = 0.f;
#pragma unroll 4
    for (int i = 0; i < CHUNK_; i++) {
        size_t off = base + (size_t)i * DIN_;
        float dt = g_dt[off];
        float ae = expf(Ac * dt);
        float s  = g_xconv[off] * dt * ae;
        g_ae[off] = ae;
        g_s[off]  = s;
        sum += s;
    }
    g_csum[((size_t)b * NCHUNK_ + ch) * DIN_ + c] = sum;
}

// ---------------- scan phase 2: exclusive prefix over chunks ------------------
__global__ void __launch_bounds__(256)
scan_phase2()
{
    int idx = blockIdx.x * blockDim.x + threadIdx.x;  // over B_*DIN_
    int c = idx % DIN_;
    int b = idx / DIN_;
    float run = 0.f;
    for (int ch = 0; ch < NCHUNK_; ch++) {
        size_t o = ((size_t)b * NCHUNK_ + ch) * DIN_ + c;
        float v = g_csum[o];
        g_cpre[o] = run;
        run += v;
    }
}

// ---------------- scan phase 3: y = cumsum*ae + xc*Dp, * silu(z) --------------
__global__ void __launch_bounds__(256)
scan_phase3(const float* __restrict__ Dp)
{
    const int ct = blockIdx.y % (DIN_ / 256);
    const int b  = blockIdx.y / (DIN_ / 256);
    const int ch = blockIdx.x;
    const int c  = ct * 256 + threadIdx.x;
    const float Dc = __ldg(&Dp[c]);
    float run = g_cpre[((size_t)b * NCHUNK_ + ch) * DIN_ + c];
    size_t base  = ((size_t)b * L_ + (size_t)ch * CHUNK_) * DIN_ + c;
    size_t zbase = ((size_t)b * L_ + (size_t)ch * CHUNK_) * (2 * DIN_) + DIN_ + c;
#pragma unroll 4
    for (int i = 0; i < CHUNK_; i++) {
        size_t off = base + (size_t)i * DIN_;
        run += g_s[off];
        float xc = g_xconv[off];
        float y  = run * g_ae[off] + xc * Dc;
        float z  = g_xz[zbase + (size_t)i * (2 * DIN_)];
        y *= silu_f(z);
        g_y[off] = y;
    }
}

// ---------------------------------------------------------------------------
extern "C" void kernel_launch(void* const* d_in, const int* in_sizes, int n_in,
                              void* d_out, int out_size)
{
    const float* x      = (const float*)d_in[0];
    const float* W_in   = (const float*)d_in[1];
    const float* W_out  = (const float*)d_in[2];
    const float* conv_w = (const float*)d_in[3];
    const float* conv_b = (const float*)d_in[4];
    const float* dt_w   = (const float*)d_in[5];
    const float* dt_b   = (const float*)d_in[6];
    const float* Aw     = (const float*)d_in[7];
    const float* Dp     = (const float*)d_in[8];
    float* out = (float*)d_out;

    float *p_xz, *p_xconv, *p_dt, *p_y;
    cudaGetSymbolAddress((void**)&p_xz, g_xz);
    cudaGetSymbolAddress((void**)&p_xconv, g_xconv);
    cudaGetSymbolAddress((void**)&p_dt, g_dt);
    cudaGetSymbolAddress((void**)&p_y, g_y);

    // 1) in_proj: xz[M,3072] = x[M,1024] @ W_in^T
    sgemm_nt<0><<<dim3((2 * DIN_) / 128, M_ / 128), 256>>>(
        x, W_in, p_xz, nullptr, M_, 2 * DIN_, DIM_);

    // 2) depthwise conv3 + bias + SiLU
    conv_silu_kernel<<<(M_ * DIN_) / 256, 256>>>(conv_w, conv_b);

    // 3) dt = softplus(x_conv @ dt_w^T + dt_b)   (fused epilogue)
    sgemm_nt<1><<<dim3(DIN_ / 128, M_ / 128), 256>>>(
        p_xconv, dt_w, p_dt, dt_b, M_, DIN_, DIN_);

    // 4) chunked cumsum scan + gating
    scan_phase1<<<dim3(NCHUNK_, B_ * (DIN_ / 256)), 256>>>(Aw);
    scan_phase2<<<(B_ * DIN_) / 256, 256>>>();
    scan_phase3<<<dim3(NCHUNK_, B_ * (DIN_ / 256)), 256>>>(Dp);

    // 5) out_proj: out[M,1024] = y[M,1536] @ W_out^T
    sgemm_nt<0><<<dim3(DIM_ / 128, M_ / 128), 256>>>(
        p_y, W_out, out, nullptr, M_, DIM_, DIN_);
}

// round 7
// speedup vs baseline: 2.6534x; 2.6534x over previous
#include <cuda_runtime.h>
#include <cuda_bf16.h>
#include <math.h>
#include <stdint.h>

#define DIM_  1024
#define DIN_  1536
#define B_    4
#define L_    4096
#define M_    (B_ * L_)          // 16384
#define NCHUNK_ 32
#define CHUNK_  (L_ / NCHUNK_)   // 128

typedef __nv_bfloat16 bf16;

// ---------------- static scratch (no allocations allowed) ----------------
__device__ __align__(16) float g_xz[(size_t)M_ * 2 * DIN_];   // in_proj out [M,3072]
__device__ __align__(16) bf16  g_xch[(size_t)M_ * DIN_];      // silu(conv) hi
__device__ __align__(16) bf16  g_xcl[(size_t)M_ * DIN_];      // silu(conv) lo
__device__ __align__(16) float g_dt[(size_t)M_ * DIN_];
__device__ __align__(16) float g_s[(size_t)M_ * DIN_];
__device__ __align__(16) float g_ae[(size_t)M_ * DIN_];
__device__ __align__(16) bf16  g_yh[(size_t)M_ * DIN_];
__device__ __align__(16) bf16  g_yl[(size_t)M_ * DIN_];
__device__ __align__(16) bf16  g_xh[(size_t)M_ * DIM_];
__device__ __align__(16) bf16  g_xl[(size_t)M_ * DIM_];
__device__ __align__(16) bf16  g_wih[(size_t)2 * DIN_ * DIM_];
__device__ __align__(16) bf16  g_wil[(size_t)2 * DIN_ * DIM_];
__device__ __align__(16) bf16  g_dwh[(size_t)DIN_ * DIN_];
__device__ __align__(16) bf16  g_dwl[(size_t)DIN_ * DIN_];
__device__ __align__(16) bf16  g_woh[(size_t)DIM_ * DIN_];
__device__ __align__(16) bf16  g_wol[(size_t)DIM_ * DIN_];
__device__ float g_csum[B_ * NCHUNK_ * DIN_];
__device__ float g_cpre[B_ * NCHUNK_ * DIN_];

__device__ __forceinline__ float softplus_f(float v) {
    return v > 20.f ? v : log1pf(expf(v));
}
__device__ __forceinline__ float silu_f(float v) {
    return v / (1.f + expf(-v));
}
__device__ __forceinline__ void split_bf16(float v, bf16& h, bf16& l) {
    h = __float2bfloat16_rn(v);
    l = __float2bfloat16_rn(v - __bfloat162float(h));
}

// ======================= PTX helpers (portable sm_80+) =======================
__device__ __forceinline__ uint32_t smem_u32(const void* p) {
    uint32_t a;
    asm("{ .reg .u64 t; cvta.to.shared.u64 t, %1; cvt.u32.u64 %0, t; }" : "=r"(a) : "l"(p));
    return a;
}
#define CP16(saddr, gptr) \
    asm volatile("cp.async.cg.shared.global [%0], [%1], 16;" :: "r"(saddr), "l"(gptr))
#define CP_COMMIT() asm volatile("cp.async.commit_group;" ::: "memory")
#define CP_WAIT1()  asm volatile("cp.async.wait_group 1;" ::: "memory")

#define LDSM4(r, a) \
    asm volatile("ldmatrix.sync.aligned.m8n8.x4.shared.b16 {%0,%1,%2,%3}, [%4];" \
        : "=r"((r)[0]), "=r"((r)[1]), "=r"((r)[2]), "=r"((r)[3]) : "r"(a))

#define MMA_BF16(d, a, b0v, b1v) \
    asm volatile("mma.sync.aligned.m16n8k16.row.col.f32.bf16.bf16.f32 " \
        "{%0,%1,%2,%3}, {%4,%5,%6,%7}, {%8,%9}, {%0,%1,%2,%3};" \
        : "+f"((d)[0]), "+f"((d)[1]), "+f"((d)[2]), "+f"((d)[3]) \
        : "r"((a)[0]), "r"((a)[1]), "r"((a)[2]), "r"((a)[3]), "r"(b0v), "r"(b1v))

__device__ __forceinline__ uint32_t sw64(uint32_t off) {
    return off ^ ((off >> 3) & 0x30);
}

// ======================= 3x-bf16 mma.sync GEMM =======================
// C[m,n] = sum_k (Ah+Al)[m,k] * (Bh+Bl)[n,k], both K-contiguous bf16.
// Block 128x128, BK=32, 256 threads (8 warps: 2 M x 4 N, warp tile 64x32).
// 3-stage cp.async pipeline. SW64-swizzled smem (64B rows).
#define BK_      32
#define STAGES_  3
#define STAGE_B  32768          // Ah 8K | Al 8K | Bh 8K | Bl 8K
#define AH_OFF   0
#define AL_OFF   8192
#define BH_OFF   16384
#define BL_OFF   24576
#define GEMM_SMEM (STAGES_ * STAGE_B)

__device__ __forceinline__ void load_stage(
    uint32_t sb, const bf16* __restrict__ Ah, const bf16* __restrict__ Al,
    const bf16* __restrict__ Bh, const bf16* __restrict__ Bl,
    int row0, int col0, int k0, int K, int tid)
{
#pragma unroll
    for (int i = 0; i < 2; ++i) {
        const int idx = tid + i * 256;          // 0..511
        const int r  = idx >> 2;                // 0..127
        const int kg = idx & 3;                 // 16B group along K
        const uint32_t so = sw64((uint32_t)(r * 64 + kg * 16));
        const size_t ga = (size_t)(row0 + r) * K + k0 + kg * 8;
        const size_t gb = (size_t)(col0 + r) * K + k0 + kg * 8;
        CP16(sb + AH_OFF + so, Ah + ga);
        CP16(sb + AL_OFF + so, Al + ga);
        CP16(sb + BH_OFF + so, Bh + gb);
        CP16(sb + BL_OFF + so, Bl + gb);
    }
}

// MODE 0: plain store.  MODE 1: softplus(acc + bias[n]).
template <int MODE>
__global__ void __launch_bounds__(256)
bf16_gemm(const bf16* __restrict__ Ah, const bf16* __restrict__ Al,
          const bf16* __restrict__ Bh, const bf16* __restrict__ Bl,
          float* __restrict__ C, const float* __restrict__ bias,
          int M, int N, int K)
{
    extern __shared__ char smem_raw[];
    const uint32_t smb = smem_u32(smem_raw);
    const int tid  = threadIdx.x;
    const int lane = tid & 31;
    const int wid  = tid >> 5;
    const int wm   = (wid >> 2) * 64;   // warp M base within block
    const int wn   = (wid & 3) * 32;    // warp N base within block
    const int row0 = blockIdx.y * 128;
    const int col0 = blockIdx.x * 128;
    const int nch  = K / BK_;

    float acc[4][4][4];
#pragma unroll
    for (int i = 0; i < 4; ++i)
#pragma unroll
        for (int j = 0; j < 4; ++j)
#pragma unroll
            for (int t = 0; t < 4; ++t) acc[i][j][t] = 0.f;

    // prologue: chunks 0,1
    load_stage(smb, Ah, Al, Bh, Bl, row0, col0, 0, K, tid);
    CP_COMMIT();
    load_stage(smb + STAGE_B, Ah, Al, Bh, Bl, row0, col0, BK_, K, tid);
    CP_COMMIT();

    // per-lane ldmatrix address offsets (tile-local, before swizzle)
    const int a_row = (lane & 7) + ((lane >> 3) & 1) * 8;    // within 16-row mtile
    const int a_kof = ((lane >> 4) & 1) * 16;                // bytes
    const int b_row = (lane & 7) + ((lane >> 4) & 1) * 8;    // within 16-row npair
    const int b_kof = ((lane >> 3) & 1) * 16;                // bytes

    for (int c = 0; c < nch; ++c) {
        CP_WAIT1();
        __syncthreads();
        if (c + 2 < nch)
            load_stage(smb + ((c + 2) % STAGES_) * STAGE_B,
                       Ah, Al, Bh, Bl, row0, col0, (c + 2) * BK_, K, tid);
        CP_COMMIT();

        const uint32_t sb = smb + (c % STAGES_) * STAGE_B;
#pragma unroll
        for (int ks = 0; ks < 2; ++ks) {
            const int kb = ks * 32;   // byte offset of this k16 within 64B row
            uint32_t fAh[4][4], fAl[4][4];
#pragma unroll
            for (int mt = 0; mt < 4; ++mt) {
                const uint32_t off = sw64((uint32_t)((wm + mt * 16 + a_row) * 64 + kb + a_kof));
                LDSM4(fAh[mt], sb + AH_OFF + off);
                LDSM4(fAl[mt], sb + AL_OFF + off);
            }
            uint32_t fBh[2][4], fBl[2][4];
#pragma unroll
            for (int np = 0; np < 2; ++np) {
                const uint32_t off = sw64((uint32_t)((wn + np * 16 + b_row) * 64 + kb + b_kof));
                LDSM4(fBh[np], sb + BH_OFF + off);
                LDSM4(fBl[np], sb + BL_OFF + off);
            }
#pragma unroll
            for (int mt = 0; mt < 4; ++mt)
#pragma unroll
                for (int nt = 0; nt < 4; ++nt) {
                    const int np = nt >> 1, rr = (nt & 1) * 2;
                    MMA_BF16(acc[mt][nt], fAh[mt], fBh[np][rr], fBh[np][rr + 1]);
                    MMA_BF16(acc[mt][nt], fAh[mt], fBl[np][rr], fBl[np][rr + 1]);
                    MMA_BF16(acc[mt][nt], fAl[mt], fBh[np][rr], fBh[np][rr + 1]);
                }
        }
    }

    // epilogue: direct float2 stores
#pragma unroll
    for (int mt = 0; mt < 4; ++mt) {
        const int r0 = row0 + wm + mt * 16 + (lane >> 2);
#pragma unroll
        for (int nt = 0; nt < 4; ++nt) {
            const int cc = col0 + wn + nt * 8 + (lane & 3) * 2;
            float v0 = acc[mt][nt][0], v1 = acc[mt][nt][1];
            float v2 = acc[mt][nt][2], v3 = acc[mt][nt][3];
            if (MODE == 1) {
                const float b0 = __ldg(&bias[cc]), b1 = __ldg(&bias[cc + 1]);
                v0 = softplus_f(v0 + b0); v1 = softplus_f(v1 + b1);
                v2 = softplus_f(v2 + b0); v3 = softplus_f(v3 + b1);
            }
            *(float2*)&C[(size_t)r0 * N + cc]       = make_float2(v0, v1);
            *(float2*)&C[(size_t)(r0 + 8) * N + cc] = make_float2(v2, v3);
        }
    }
}

// ---------------- hi/lo bf16 split -----------------------
__global__ void __launch_bounds__(256)
split_kernel(const float* __restrict__ src, bf16* __restrict__ hi,
             bf16* __restrict__ lo, int n)
{
    int i = blockIdx.x * blockDim.x + threadIdx.x;
    if (i < n) {
        bf16 h, l;
        split_bf16(src[i], h, l);
        hi[i] = h;
        lo[i] = l;
    }
}

// ---------------- depthwise conv3 (pad=1) + bias + SiLU + split -----------
__global__ void __launch_bounds__(256)
conv_silu_kernel(const float* __restrict__ cw, const float* __restrict__ cb)
{
    int idx = blockIdx.x * blockDim.x + threadIdx.x;  // over M_*DIN_
    int c  = idx % DIN_;
    int bl = idx / DIN_;
    int l  = bl % L_;
    const float* base = g_xz + (size_t)bl * (2 * DIN_) + c;
    float x0 = base[0];
    float xm = (l > 0)      ? base[-(2 * DIN_)] : 0.f;
    float xp = (l < L_ - 1) ? base[ (2 * DIN_)] : 0.f;
    float w0 = __ldg(&cw[c * 3 + 0]);
    float w1 = __ldg(&cw[c * 3 + 1]);
    float w2 = __ldg(&cw[c * 3 + 2]);
    float v = fmaf(w0, xm, fmaf(w1, x0, fmaf(w2, xp, __ldg(&cb[c]))));
    v = silu_f(v);
    bf16 h, lo;
    split_bf16(v, h, lo);
    g_xch[idx] = h;
    g_xcl[idx] = lo;
}

// ---------------- scan phase 1 -------------------------------------------
__global__ void __launch_bounds__(256)
scan_phase1(const float* __restrict__ Aw)
{
    const int ct = blockIdx.y % (DIN_ / 256);
    const int b  = blockIdx.y / (DIN_ / 256);
    const int ch = blockIdx.x;
    const int c  = ct * 256 + threadIdx.x;
    const float Ac = __ldg(&Aw[c]);
    size_t base = ((size_t)b * L_ + (size_t)ch * CHUNK_) * DIN_ + c;
    float sum = 0.f;
#pragma unroll 4
    for (int i = 0; i < CHUNK_; i++) {
        size_t off = base + (size_t)i * DIN_;
        float dt = g_dt[off];
        float xc = __bfloat162float(g_xch[off]) + __bfloat162float(g_xcl[off]);
        float ae = expf(Ac * dt);
        float s  = xc * dt * ae;
        g_ae[off] = ae;
        g_s[off]  = s;
        sum += s;
    }
    g_csum[((size_t)b * NCHUNK_ + ch) * DIN_ + c] = sum;
}

// ---------------- scan phase 2: exclusive prefix over chunks --------------
__global__ void __launch_bounds__(256)
scan_phase2()
{
    int idx = blockIdx.x * blockDim.x + threadIdx.x;  // over B_*DIN_
    int c = idx % DIN_;
    int b = idx / DIN_;
    float run = 0.f;
    for (int ch = 0; ch < NCHUNK_; ch++) {
        size_t o = ((size_t)b * NCHUNK_ + ch) * DIN_ + c;
        float v = g_csum[o];
        g_cpre[o] = run;
        run += v;
    }
}

// ---------------- scan phase 3: y = cumsum*ae + xc*Dp, * silu(z), split ---
__global__ void __launch_bounds__(256)
scan_phase3(const float* __restrict__ Dp)
{
    const int ct = blockIdx.y % (DIN_ / 256);
    const int b  = blockIdx.y / (DIN_ / 256);
    const int ch = blockIdx.x;
    const int c  = ct * 256 + threadIdx.x;
    const float Dc = __ldg(&Dp[c]);
    float run = g_cpre[((size_t)b * NCHUNK_ + ch) * DIN_ + c];
    size_t base  = ((size_t)b * L_ + (size_t)ch * CHUNK_) * DIN_ + c;
    size_t zbase = ((size_t)b * L_ + (size_t)ch * CHUNK_) * (2 * DIN_) + DIN_ + c;
#pragma unroll 4
    for (int i = 0; i < CHUNK_; i++) {
        size_t off = base + (size_t)i * DIN_;
        run += g_s[off];
        float xc = __bfloat162float(g_xch[off]) + __bfloat162float(g_xcl[off]);
        float y  = run * g_ae[off] + xc * Dc;
        float z  = g_xz[zbase + (size_t)i * (2 * DIN_)];
        y *= silu_f(z);
        bf16 h, lo;
        split_bf16(y, h, lo);
        g_yh[off] = h;
        g_yl[off] = lo;
    }
}

// ---------------------------------------------------------------------------
extern "C" void kernel_launch(void* const* d_in, const int* in_sizes, int n_in,
                              void* d_out, int out_size)
{
    const float* x      = (const float*)d_in[0];
    const float* W_in   = (const float*)d_in[1];
    const float* W_out  = (const float*)d_in[2];
    const float* conv_w = (const float*)d_in[3];
    const float* conv_b = (const float*)d_in[4];
    const float* dt_w   = (const float*)d_in[5];
    const float* dt_b   = (const float*)d_in[6];
    const float* Aw     = (const float*)d_in[7];
    const float* Dp     = (const float*)d_in[8];
    float* out = (float*)d_out;

    float *p_xz, *p_dt;
    bf16 *p_xh, *p_xl, *p_wih, *p_wil, *p_dwh, *p_dwl, *p_woh, *p_wol;
    bf16 *p_xch, *p_xcl, *p_yh, *p_yl;
    cudaGetSymbolAddress((void**)&p_xz, g_xz);
    cudaGetSymbolAddress((void**)&p_dt, g_dt);
    cudaGetSymbolAddress((void**)&p_xh, g_xh);
    cudaGetSymbolAddress((void**)&p_xl, g_xl);
    cudaGetSymbolAddress((void**)&p_wih, g_wih);
    cudaGetSymbolAddress((void**)&p_wil, g_wil);
    cudaGetSymbolAddress((void**)&p_dwh, g_dwh);
    cudaGetSymbolAddress((void**)&p_dwl, g_dwl);
    cudaGetSymbolAddress((void**)&p_woh, g_woh);
    cudaGetSymbolAddress((void**)&p_wol, g_wol);
    cudaGetSymbolAddress((void**)&p_xch, g_xch);
    cudaGetSymbolAddress((void**)&p_xcl, g_xcl);
    cudaGetSymbolAddress((void**)&p_yh, g_yh);
    cudaGetSymbolAddress((void**)&p_yl, g_yl);

    cudaFuncSetAttribute(bf16_gemm<0>, cudaFuncAttributeMaxDynamicSharedMemorySize, GEMM_SMEM);
    cudaFuncSetAttribute(bf16_gemm<1>, cudaFuncAttributeMaxDynamicSharedMemorySize, GEMM_SMEM);

    // 0) bf16 hi/lo splits
    split_kernel<<<(M_ * DIM_) / 256, 256>>>(x, p_xh, p_xl, M_ * DIM_);
    split_kernel<<<(2 * DIN_ * DIM_) / 256, 256>>>(W_in, p_wih, p_wil, 2 * DIN_ * DIM_);
    split_kernel<<<(DIN_ * DIN_) / 256, 256>>>(dt_w, p_dwh, p_dwl, DIN_ * DIN_);
    split_kernel<<<(DIM_ * DIN_) / 256, 256>>>(W_out, p_woh, p_wol, DIM_ * DIN_);

    // 1) in_proj: xz[M,3072] = x @ W_in^T   (3x-bf16 mma)
    bf16_gemm<0><<<dim3((2 * DIN_) / 128, M_ / 128), 256, GEMM_SMEM>>>(
        p_xh, p_xl, p_wih, p_wil, p_xz, nullptr, M_, 2 * DIN_, DIM_);

    // 2) depthwise conv3 + bias + SiLU (+ split)
    conv_silu_kernel<<<(M_ * DIN_) / 256, 256>>>(conv_w, conv_b);

    // 3) dt = softplus(x_conv @ dt_w^T + dt_b)  (fused epilogue)
    bf16_gemm<1><<<dim3(DIN_ / 128, M_ / 128), 256, GEMM_SMEM>>>(
        p_xch, p_xcl, p_dwh, p_dwl, p_dt, dt_b, M_, DIN_, DIN_);

    // 4) chunked cumsum scan + gating (y written as bf16 hi/lo)
    scan_phase1<<<dim3(NCHUNK_, B_ * (DIN_ / 256)), 256>>>(Aw);
    scan_phase2<<<(B_ * DIN_) / 256, 256>>>();
    scan_phase3<<<dim3(NCHUNK_, B_ * (DIN_ / 256)), 256>>>(Dp);

    // 5) out_proj: out[M,1024] = y @ W_out^T
    bf16_gemm<0><<<dim3(DIM_ / 128, M_ / 128), 256, GEMM_SMEM>>>(
        p_yh, p_yl, p_woh, p_wol, out, nullptr, M_, DIM_, DIN_);
}

// round 8
// speedup vs baseline: 2.9362x; 1.1066x over previous
#include <cuda_runtime.h>
#include <cuda_bf16.h>
#include <math.h>
#include <stdint.h>

#define DIM_  1024
#define DIN_  1536
#define B_    4
#define L_    4096
#define M_    (B_ * L_)          // 16384
#define NCHUNK_ 32
#define CHUNK_  (L_ / NCHUNK_)   // 128

typedef __nv_bfloat16 bf16;

// ---------------- static scratch (no allocations allowed) ----------------
__device__ __align__(16) float g_xz[(size_t)M_ * 2 * DIN_];   // in_proj out [M,3072]
__device__ __align__(16) bf16  g_xch[(size_t)M_ * DIN_];      // silu(conv) hi
__device__ __align__(16) bf16  g_xcl[(size_t)M_ * DIN_];      // silu(conv) lo
__device__ __align__(16) float g_dt[(size_t)M_ * DIN_];
__device__ __align__(16) float g_s[(size_t)M_ * DIN_];
__device__ __align__(16) float g_ae[(size_t)M_ * DIN_];
__device__ __align__(16) bf16  g_yh[(size_t)M_ * DIN_];
__device__ __align__(16) bf16  g_yl[(size_t)M_ * DIN_];
__device__ __align__(16) bf16  g_xh[(size_t)M_ * DIM_];
__device__ __align__(16) bf16  g_xl[(size_t)M_ * DIM_];
__device__ __align__(16) bf16  g_wih[(size_t)2 * DIN_ * DIM_];
__device__ __align__(16) bf16  g_wil[(size_t)2 * DIN_ * DIM_];
__device__ __align__(16) bf16  g_dwh[(size_t)DIN_ * DIN_];
__device__ __align__(16) bf16  g_dwl[(size_t)DIN_ * DIN_];
__device__ __align__(16) bf16  g_woh[(size_t)DIM_ * DIN_];
__device__ __align__(16) bf16  g_wol[(size_t)DIM_ * DIN_];
__device__ float g_csum[B_ * NCHUNK_ * DIN_];
__device__ float g_cpre[B_ * NCHUNK_ * DIN_];

__device__ __forceinline__ float softplus_f(float v) {
    return v > 20.f ? v : log1pf(expf(v));
}
__device__ __forceinline__ float silu_f(float v) {
    return v / (1.f + expf(-v));
}
__device__ __forceinline__ void split_bf16(float v, bf16& h, bf16& l) {
    h = __float2bfloat16_rn(v);
    l = __float2bfloat16_rn(v - __bfloat162float(h));
}

// ======================= PTX helpers (portable sm_80+) =======================
__device__ __forceinline__ uint32_t smem_u32(const void* p) {
    uint32_t a;
    asm("{ .reg .u64 t; cvta.to.shared.u64 t, %1; cvt.u32.u64 %0, t; }" : "=r"(a) : "l"(p));
    return a;
}
#define CP16(saddr, gptr) \
    asm volatile("cp.async.cg.shared.global [%0], [%1], 16;" :: "r"(saddr), "l"(gptr))
#define CP_COMMIT() asm volatile("cp.async.commit_group;" ::: "memory")
#define CP_WAIT1()  asm volatile("cp.async.wait_group 1;" ::: "memory")

#define LDSM4(r, a) \
    asm volatile("ldmatrix.sync.aligned.m8n8.x4.shared.b16 {%0,%1,%2,%3}, [%4];" \
        : "=r"((r)[0]), "=r"((r)[1]), "=r"((r)[2]), "=r"((r)[3]) : "r"(a))

#define MMA_BF16(d, a, b0v, b1v) \
    asm volatile("mma.sync.aligned.m16n8k16.row.col.f32.bf16.bf16.f32 " \
        "{%0,%1,%2,%3}, {%4,%5,%6,%7}, {%8,%9}, {%0,%1,%2,%3};" \
        : "+f"((d)[0]), "+f"((d)[1]), "+f"((d)[2]), "+f"((d)[3]) \
        : "r"((a)[0]), "r"((a)[1]), "r"((a)[2]), "r"((a)[3]), "r"(b0v), "r"(b1v))

__device__ __forceinline__ uint32_t sw64(uint32_t off) {
    return off ^ ((off >> 3) & 0x30);
}

// ======================= 3x-bf16 mma.sync GEMM =======================
// C[m,n] = sum_k (Ah+Al)[m,k] * (Bh+Bl)[n,k], both K-contiguous bf16.
// Block 128x128, BK=32, 256 threads (8 warps: 2 M x 4 N, warp tile 64x32).
// 3-stage cp.async pipeline, 2 CTAs/SM (4 warps/SMSP for latency hiding).
#define BK_      32
#define STAGES_  3
#define STAGE_B  32768          // Ah 8K | Al 8K | Bh 8K | Bl 8K
#define AH_OFF   0
#define AL_OFF   8192
#define BH_OFF   16384
#define BL_OFF   24576
#define GEMM_SMEM (STAGES_ * STAGE_B)

__device__ __forceinline__ void load_stage(
    uint32_t sb, const bf16* __restrict__ Ah, const bf16* __restrict__ Al,
    const bf16* __restrict__ Bh, const bf16* __restrict__ Bl,
    int row0, int col0, int k0, int K, int tid)
{
#pragma unroll
    for (int i = 0; i < 2; ++i) {
        const int idx = tid + i * 256;          // 0..511
        const int r  = idx >> 2;                // 0..127
        const int kg = idx & 3;                 // 16B group along K
        const uint32_t so = sw64((uint32_t)(r * 64 + kg * 16));
        const size_t ga = (size_t)(row0 + r) * K + k0 + kg * 8;
        const size_t gb = (size_t)(col0 + r) * K + k0 + kg * 8;
        CP16(sb + AH_OFF + so, Ah + ga);
        CP16(sb + AL_OFF + so, Al + ga);
        CP16(sb + BH_OFF + so, Bh + gb);
        CP16(sb + BL_OFF + so, Bl + gb);
    }
}

// MODE 0: plain store.  MODE 1: softplus(acc + bias[n]).
template <int MODE>
__global__ void __launch_bounds__(256, 2)
bf16_gemm(const bf16* __restrict__ Ah, const bf16* __restrict__ Al,
          const bf16* __restrict__ Bh, const bf16* __restrict__ Bl,
          float* __restrict__ C, const float* __restrict__ bias,
          int M, int N, int K)
{
    extern __shared__ char smem_raw[];
    const uint32_t smb = smem_u32(smem_raw);
    const int tid  = threadIdx.x;
    const int lane = tid & 31;
    const int wid  = tid >> 5;
    const int wm   = (wid >> 2) * 64;   // warp M base within block
    const int wn   = (wid & 3) * 32;    // warp N base within block
    const int row0 = blockIdx.y * 128;
    const int col0 = blockIdx.x * 128;
    const int nch  = K / BK_;

    float acc[4][4][4];
#pragma unroll
    for (int i = 0; i < 4; ++i)
#pragma unroll
        for (int j = 0; j < 4; ++j)
#pragma unroll
            for (int t = 0; t < 4; ++t) acc[i][j][t] = 0.f;

    // prologue: chunks 0,1
    load_stage(smb, Ah, Al, Bh, Bl, row0, col0, 0, K, tid);
    CP_COMMIT();
    load_stage(smb + STAGE_B, Ah, Al, Bh, Bl, row0, col0, BK_, K, tid);
    CP_COMMIT();

    // per-lane ldmatrix address offsets (tile-local, before swizzle)
    const int a_row = (lane & 7) + ((lane >> 3) & 1) * 8;    // within 16-row mtile
    const int a_kof = ((lane >> 4) & 1) * 16;                // bytes
    const int b_row = (lane & 7) + ((lane >> 4) & 1) * 8;    // within 16-row npair
    const int b_kof = ((lane >> 3) & 1) * 16;                // bytes

    for (int c = 0; c < nch; ++c) {
        CP_WAIT1();
        __syncthreads();
        if (c + 2 < nch)
            load_stage(smb + ((c + 2) % STAGES_) * STAGE_B,
                       Ah, Al, Bh, Bl, row0, col0, (c + 2) * BK_, K, tid);
        CP_COMMIT();

        const uint32_t sb = smb + (c % STAGES_) * STAGE_B;
#pragma unroll
        for (int ks = 0; ks < 2; ++ks) {
            const int kb = ks * 32;   // byte offset of this k16 within 64B row
            uint32_t fBh[2][4], fBl[2][4];
#pragma unroll
            for (int np = 0; np < 2; ++np) {
                const uint32_t off = sw64((uint32_t)((wn + np * 16 + b_row) * 64 + kb + b_kof));
                LDSM4(fBh[np], sb + BH_OFF + off);
                LDSM4(fBl[np], sb + BL_OFF + off);
            }
            // A fragments loaded per-mt and reused (keeps regs <= 128 for occ 2)
#pragma unroll
            for (int mt = 0; mt < 4; ++mt) {
                uint32_t fAh[4], fAl[4];
                const uint32_t off = sw64((uint32_t)((wm + mt * 16 + a_row) * 64 + kb + a_kof));
                LDSM4(fAh, sb + AH_OFF + off);
                LDSM4(fAl, sb + AL_OFF + off);
#pragma unroll
                for (int nt = 0; nt < 4; ++nt) {
                    const int np = nt >> 1, rr = (nt & 1) * 2;
                    MMA_BF16(acc[mt][nt], fAh, fBh[np][rr], fBh[np][rr + 1]);
                    MMA_BF16(acc[mt][nt], fAh, fBl[np][rr], fBl[np][rr + 1]);
                    MMA_BF16(acc[mt][nt], fAl, fBh[np][rr], fBh[np][rr + 1]);
                }
            }
        }
    }

    // epilogue: direct float2 stores
#pragma unroll
    for (int mt = 0; mt < 4; ++mt) {
        const int r0 = row0 + wm + mt * 16 + (lane >> 2);
#pragma unroll
        for (int nt = 0; nt < 4; ++nt) {
            const int cc = col0 + wn + nt * 8 + (lane & 3) * 2;
            float v0 = acc[mt][nt][0], v1 = acc[mt][nt][1];
            float v2 = acc[mt][nt][2], v3 = acc[mt][nt][3];
            if (MODE == 1) {
                const float b0 = __ldg(&bias[cc]), b1 = __ldg(&bias[cc + 1]);
                v0 = softplus_f(v0 + b0); v1 = softplus_f(v1 + b1);
                v2 = softplus_f(v2 + b0); v3 = softplus_f(v3 + b1);
            }
            *(float2*)&C[(size_t)r0 * N + cc]       = make_float2(v0, v1);
            *(float2*)&C[(size_t)(r0 + 8) * N + cc] = make_float2(v2, v3);
        }
    }
}

// ---------------- fused hi/lo bf16 split of all four fp32 sources ----------
#define N0_ (M_ * DIM_)            // x
#define N1_ (2 * DIN_ * DIM_)      // W_in
#define N2_ (DIN_ * DIN_)          // dt_w
#define N3_ (DIM_ * DIN_)          // W_out
#define NSPLIT4_ ((N0_ + N1_ + N2_ + N3_) / 4)

__device__ __forceinline__ void split4_store(const float4 v, bf16* hi, bf16* lo, int i4)
{
    bf16 h0, l0, h1, l1, h2, l2, h3, l3;
    split_bf16(v.x, h0, l0); split_bf16(v.y, h1, l1);
    split_bf16(v.z, h2, l2); split_bf16(v.w, h3, l3);
    ushort4 hv = make_ushort4(__bfloat16_as_ushort(h0), __bfloat16_as_ushort(h1),
                              __bfloat16_as_ushort(h2), __bfloat16_as_ushort(h3));
    ushort4 lv = make_ushort4(__bfloat16_as_ushort(l0), __bfloat16_as_ushort(l1),
                              __bfloat16_as_ushort(l2), __bfloat16_as_ushort(l3));
    *(ushort4*)&hi[i4 * 4] = hv;
    *(ushort4*)&lo[i4 * 4] = lv;
}

__global__ void __launch_bounds__(256)
split_all_kernel(const float* __restrict__ x, const float* __restrict__ W_in,
                 const float* __restrict__ dt_w, const float* __restrict__ W_out)
{
    int i = blockIdx.x * blockDim.x + threadIdx.x;
    if (i >= NSPLIT4_) return;
    if (i < N0_ / 4) {
        split4_store(*(const float4*)&x[i * 4], g_xh, g_xl, i);
    } else if (i < (N0_ + N1_) / 4) {
        int j = i - N0_ / 4;
        split4_store(*(const float4*)&W_in[j * 4], g_wih, g_wil, j);
    } else if (i < (N0_ + N1_ + N2_) / 4) {
        int j = i - (N0_ + N1_) / 4;
        split4_store(*(const float4*)&dt_w[j * 4], g_dwh, g_dwl, j);
    } else {
        int j = i - (N0_ + N1_ + N2_) / 4;
        split4_store(*(const float4*)&W_out[j * 4], g_woh, g_wol, j);
    }
}

// ---------------- depthwise conv3 (pad=1) + bias + SiLU + split -----------
__global__ void __launch_bounds__(256)
conv_silu_kernel(const float* __restrict__ cw, const float* __restrict__ cb)
{
    int idx = blockIdx.x * blockDim.x + threadIdx.x;  // over M_*DIN_
    int c  = idx % DIN_;
    int bl = idx / DIN_;
    int l  = bl % L_;
    const float* base = g_xz + (size_t)bl * (2 * DIN_) + c;
    float x0 = base[0];
    float xm = (l > 0)      ? base[-(2 * DIN_)] : 0.f;
    float xp = (l < L_ - 1) ? base[ (2 * DIN_)] : 0.f;
    float w0 = __ldg(&cw[c * 3 + 0]);
    float w1 = __ldg(&cw[c * 3 + 1]);
    float w2 = __ldg(&cw[c * 3 + 2]);
    float v = fmaf(w0, xm, fmaf(w1, x0, fmaf(w2, xp, __ldg(&cb[c]))));
    v = silu_f(v);
    bf16 h, lo;
    split_bf16(v, h, lo);
    g_xch[idx] = h;
    g_xcl[idx] = lo;
}

// ---------------- scan phase 1 -------------------------------------------
__global__ void __launch_bounds__(256)
scan_phase1(const float* __restrict__ Aw)
{
    const int ct = blockIdx.y % (DIN_ / 256);
    const int b  = blockIdx.y / (DIN_ / 256);
    const int ch = blockIdx.x;
    const int c  = ct * 256 + threadIdx.x;
    const float Ac = __ldg(&Aw[c]);
    size_t base = ((size_t)b * L_ + (size_t)ch * CHUNK_) * DIN_ + c;
    float sum = 0.f;
#pragma unroll 4
    for (int i = 0; i < CHUNK_; i++) {
        size_t off = base + (size_t)i * DIN_;
        float dt = g_dt[off];
        float xc = __bfloat162float(g_xch[off]) + __bfloat162float(g_xcl[off]);
        float ae = expf(Ac * dt);
        float s  = xc * dt * ae;
        g_ae[off] = ae;
        g_s[off]  = s;
        sum += s;
    }
    g_csum[((size_t)b * NCHUNK_ + ch) * DIN_ + c] = sum;
}

// ---------------- scan phase 2: exclusive prefix over chunks --------------
__global__ void __launch_bounds__(256)
scan_phase2()
{
    int idx = blockIdx.x * blockDim.x + threadIdx.x;  // over B_*DIN_
    int c = idx % DIN_;
    int b = idx / DIN_;
    float run = 0.f;
    for (int ch = 0; ch < NCHUNK_; ch++) {
        size_t o = ((size_t)b * NCHUNK_ + ch) * DIN_ + c;
        float v = g_csum[o];
        g_cpre[o] = run;
        run += v;
    }
}

// ---------------- scan phase 3: y = cumsum*ae + xc*Dp, * silu(z), split ---
__global__ void __launch_bounds__(256)
scan_phase3(const float* __restrict__ Dp)
{
    const int ct = blockIdx.y % (DIN_ / 256);
    const int b  = blockIdx.y / (DIN_ / 256);
    const int ch = blockIdx.x;
    const int c  = ct * 256 + threadIdx.x;
    const float Dc = __ldg(&Dp[c]);
    float run = g_cpre[((size_t)b * NCHUNK_ + ch) * DIN_ + c];
    size_t base  = ((size_t)b * L_ + (size_t)ch * CHUNK_) * DIN_ + c;
    size_t zbase = ((size_t)b * L_ + (size_t)ch * CHUNK_) * (2 * DIN_) + DIN_ + c;
#pragma unroll 4
    for (int i = 0; i < CHUNK_; i++) {
        size_t off = base + (size_t)i * DIN_;
        run += g_s[off];
        float xc = __bfloat162float(g_xch[off]) + __bfloat162float(g_xcl[off]);
        float y  = run * g_ae[off] + xc * Dc;
        float z  = g_xz[zbase + (size_t)i * (2 * DIN_)];
        y *= silu_f(z);
        bf16 h, lo;
        split_bf16(y, h, lo);
        g_yh[off] = h;
        g_yl[off] = lo;
    }
}

// ---------------------------------------------------------------------------
extern "C" void kernel_launch(void* const* d_in, const int* in_sizes, int n_in,
                              void* d_out, int out_size)
{
    const float* x      = (const float*)d_in[0];
    const float* W_in   = (const float*)d_in[1];
    const float* W_out  = (const float*)d_in[2];
    const float* conv_w = (const float*)d_in[3];
    const float* conv_b = (const float*)d_in[4];
    const float* dt_w   = (const float*)d_in[5];
    const float* dt_b   = (const float*)d_in[6];
    const float* Aw     = (const float*)d_in[7];
    const float* Dp     = (const float*)d_in[8];
    float* out = (float*)d_out;

    float *p_xz, *p_dt;
    bf16 *p_xh, *p_xl, *p_wih, *p_wil, *p_dwh, *p_dwl, *p_woh, *p_wol;
    bf16 *p_xch, *p_xcl, *p_yh, *p_yl;
    cudaGetSymbolAddress((void**)&p_xz, g_xz);
    cudaGetSymbolAddress((void**)&p_dt, g_dt);
    cudaGetSymbolAddress((void**)&p_xh, g_xh);
    cudaGetSymbolAddress((void**)&p_xl, g_xl);
    cudaGetSymbolAddress((void**)&p_wih, g_wih);
    cudaGetSymbolAddress((void**)&p_wil, g_wil);
    cudaGetSymbolAddress((void**)&p_dwh, g_dwh);
    cudaGetSymbolAddress((void**)&p_dwl, g_dwl);
    cudaGetSymbolAddress((void**)&p_woh, g_woh);
    cudaGetSymbolAddress((void**)&p_wol, g_wol);
    cudaGetSymbolAddress((void**)&p_xch, g_xch);
    cudaGetSymbolAddress((void**)&p_xcl, g_xcl);
    cudaGetSymbolAddress((void**)&p_yh, g_yh);
    cudaGetSymbolAddress((void**)&p_yl, g_yl);

    cudaFuncSetAttribute(bf16_gemm<0>, cudaFuncAttributeMaxDynamicSharedMemorySize, GEMM_SMEM);
    cudaFuncSetAttribute(bf16_gemm<1>, cudaFuncAttributeMaxDynamicSharedMemorySize, GEMM_SMEM);

    // 1) fused bf16 hi/lo splits (x, W_in, dt_w, W_out)
    split_all_kernel<<<(NSPLIT4_ + 255) / 256, 256>>>(x, W_in, dt_w, W_out);

    // 2) in_proj: xz[M,3072] = x @ W_in^T   (3x-bf16 mma)
    bf16_gemm<0><<<dim3((2 * DIN_) / 128, M_ / 128), 256, GEMM_SMEM>>>(
        p_xh, p_xl, p_wih, p_wil, p_xz, nullptr, M_, 2 * DIN_, DIM_);

    // 3) depthwise conv3 + bias + SiLU (+ split)
    conv_silu_kernel<<<(M_ * DIN_) / 256, 256>>>(conv_w, conv_b);

    // 4) dt = softplus(x_conv @ dt_w^T + dt_b)  <- launch slot 4: ncu target
    bf16_gemm<1><<<dim3(DIN_ / 128, M_ / 128), 256, GEMM_SMEM>>>(
        p_xch, p_xcl, p_dwh, p_dwl, p_dt, dt_b, M_, DIN_, DIN_);

    // 5) chunked cumsum scan + gating (y written as bf16 hi/lo)
    scan_phase1<<<dim3(NCHUNK_, B_ * (DIN_ / 256)), 256>>>(Aw);
    scan_phase2<<<(B_ * DIN_) / 256, 256>>>();
    scan_phase3<<<dim3(NCHUNK_, B_ * (DIN_ / 256)), 256>>>(Dp);

    // 6) out_proj: out[M,1024] = y @ W_out^T
    bf16_gemm<0><<<dim3(DIM_ / 128, M_ / 128), 256, GEMM_SMEM>>>(
        p_yh, p_yl, p_woh, p_wol, out, nullptr, M_, DIM_, DIN_);
}

// round 12
// speedup vs baseline: 3.0707x; 1.0458x over previous
#include <cuda_runtime.h>
#include <cuda_bf16.h>
#include <math.h>
#include <stdint.h>

#define DIM_  1024
#define DIN_  1536
#define B_    4
#define L_    4096
#define M_    (B_ * L_)          // 16384
#define NCHUNK_ 32
#define CHUNK_  (L_ / NCHUNK_)   // 128

typedef __nv_bfloat16 bf16;

// ---------------- static scratch (no allocations allowed) ----------------
__device__ __align__(16) float g_xz[(size_t)M_ * 2 * DIN_];   // in_proj out [M,3072]
__device__ __align__(16) bf16  g_xch[(size_t)M_ * DIN_];      // silu(conv) hi
__device__ __align__(16) bf16  g_xcl[(size_t)M_ * DIN_];      // silu(conv) lo
__device__ __align__(16) float g_dt[(size_t)M_ * DIN_];
__device__ __align__(16) bf16  g_yh[(size_t)M_ * DIN_];
__device__ __align__(16) bf16  g_yl[(size_t)M_ * DIN_];
__device__ __align__(16) bf16  g_xh[(size_t)M_ * DIM_];
__device__ __align__(16) bf16  g_xl[(size_t)M_ * DIM_];
__device__ __align__(16) bf16  g_wih[(size_t)2 * DIN_ * DIM_];
__device__ __align__(16) bf16  g_wil[(size_t)2 * DIN_ * DIM_];
__device__ __align__(16) bf16  g_dwh[(size_t)DIN_ * DIN_];
__device__ __align__(16) bf16  g_dwl[(size_t)DIN_ * DIN_];
__device__ __align__(16) bf16  g_woh[(size_t)DIM_ * DIN_];
__device__ __align__(16) bf16  g_wol[(size_t)DIM_ * DIN_];
__device__ float g_csum[B_ * NCHUNK_ * DIN_];
__device__ float g_cpre[B_ * NCHUNK_ * DIN_];

__device__ __forceinline__ float softplus_f(float v) {
    return v > 20.f ? v : log1pf(expf(v));
}
__device__ __forceinline__ float silu_f(float v) {
    return v / (1.f + expf(-v));
}
__device__ __forceinline__ void split_bf16(float v, bf16& h, bf16& l) {
    h = __float2bfloat16_rn(v);
    l = __float2bfloat16_rn(v - __bfloat162float(h));
}

// ======================= PTX helpers (portable sm_80+) =======================
__device__ __forceinline__ uint32_t smem_u32(const void* p) {
    uint32_t a;
    asm("{ .reg .u64 t; cvta.to.shared.u64 t, %1; cvt.u32.u64 %0, t; }" : "=r"(a) : "l"(p));
    return a;
}
#define CP16(saddr, gptr) \
    asm volatile("cp.async.cg.shared.global [%0], [%1], 16;" :: "r"(saddr), "l"(gptr))
#define CP_COMMIT() asm volatile("cp.async.commit_group;" ::: "memory")
#define CP_WAIT1()  asm volatile("cp.async.wait_group 1;" ::: "memory")

#define LDSM4(r, a) \
    asm volatile("ldmatrix.sync.aligned.m8n8.x4.shared.b16 {%0,%1,%2,%3}, [%4];" \
        : "=r"((r)[0]), "=r"((r)[1]), "=r"((r)[2]), "=r"((r)[3]) : "r"(a))

#define MMA_BF16(d, a, b0v, b1v) \
    asm volatile("mma.sync.aligned.m16n8k16.row.col.f32.bf16.bf16.f32 " \
        "{%0,%1,%2,%3}, {%4,%5,%6,%7}, {%8,%9}, {%0,%1,%2,%3};" \
        : "+f"((d)[0]), "+f"((d)[1]), "+f"((d)[2]), "+f"((d)[3]) \
        : "r"((a)[0]), "r"((a)[1]), "r"((a)[2]), "r"((a)[3]), "r"(b0v), "r"(b1v))

__device__ __forceinline__ uint32_t sw64(uint32_t off) {
    return off ^ ((off >> 3) & 0x30);
}

// ======================= 3x-bf16 mma.sync GEMM =======================
// C[m,n] = sum_k (Ah+Al)[m,k] * (Bh+Bl)[n,k], both K-contiguous bf16.
// Block 128x128, BK=32, 256 threads (8 warps: 2 M x 4 N, warp tile 64x32).
// 3-stage cp.async pipeline, 2 CTAs/SM. Product loops reordered so dependent
// MMAs into the same accumulator are 4 apart; ldmatrix addrs hoisted.
#define BK_      32
#define STAGES_  3
#define STAGE_B  32768          // Ah 8K | Al 8K | Bh 8K | Bl 8K
#define AH_OFF   0
#define AL_OFF   8192
#define BH_OFF   16384
#define BL_OFF   24576
#define GEMM_SMEM (STAGES_ * STAGE_B)

__device__ __forceinline__ void load_stage(
    uint32_t sb, const bf16* __restrict__ Ah, const bf16* __restrict__ Al,
    const bf16* __restrict__ Bh, const bf16* __restrict__ Bl,
    int row0, int col0, int k0, int K, int tid)
{
#pragma unroll
    for (int i = 0; i < 2; ++i) {
        const int idx = tid + i * 256;          // 0..511
        const int r  = idx >> 2;                // 0..127
        const int kg = idx & 3;                 // 16B group along K
        const uint32_t so = sw64((uint32_t)(r * 64 + kg * 16));
        const size_t ga = (size_t)(row0 + r) * K + k0 + kg * 8;
        const size_t gb = (size_t)(col0 + r) * K + k0 + kg * 8;
        CP16(sb + AH_OFF + so, Ah + ga);
        CP16(sb + AL_OFF + so, Al + ga);
        CP16(sb + BH_OFF + so, Bh + gb);
        CP16(sb + BL_OFF + so, Bl + gb);
    }
}

// MODE 0: plain store.  MODE 1: softplus(acc + bias[n]).
template <int MODE>
__global__ void __launch_bounds__(256, 2)
bf16_gemm(const bf16* __restrict__ Ah, const bf16* __restrict__ Al,
          const bf16* __restrict__ Bh, const bf16* __restrict__ Bl,
          float* __restrict__ C, const float* __restrict__ bias,
          int M, int N, int K)
{
    extern __shared__ char smem_raw[];
    const uint32_t smb = smem_u32(smem_raw);
    const int tid  = threadIdx.x;
    const int lane = tid & 31;
    const int wid  = tid >> 5;
    const int wm   = (wid >> 2) * 64;   // warp M base within block
    const int wn   = (wid & 3) * 32;    // warp N base within block
    const int row0 = blockIdx.y * 128;
    const int col0 = blockIdx.x * 128;
    const int nch  = K / BK_;

    float acc[4][4][4];
#pragma unroll
    for (int i = 0; i < 4; ++i)
#pragma unroll
        for (int j = 0; j < 4; ++j)
#pragma unroll
            for (int t = 0; t < 4; ++t) acc[i][j][t] = 0.f;

    // prologue: chunks 0,1
    load_stage(smb, Ah, Al, Bh, Bl, row0, col0, 0, K, tid);
    CP_COMMIT();
    load_stage(smb + STAGE_B, Ah, Al, Bh, Bl, row0, col0, BK_, K, tid);
    CP_COMMIT();

    // hoisted per-lane ldmatrix tile-local swizzled offsets
    const int a_row = (lane & 7) + ((lane >> 3) & 1) * 8;
    const int a_kof = ((lane >> 4) & 1) * 16;
    const int b_row = (lane & 7) + ((lane >> 4) & 1) * 8;
    const int b_kof = ((lane >> 3) & 1) * 16;
    uint32_t offA[2][4], offB[2][2];
#pragma unroll
    for (int ks = 0; ks < 2; ++ks) {
#pragma unroll
        for (int mt = 0; mt < 4; ++mt)
            offA[ks][mt] = AH_OFF +
                sw64((uint32_t)((wm + mt * 16 + a_row) * 64 + ks * 32 + a_kof));
#pragma unroll
        for (int np = 0; np < 2; ++np)
            offB[ks][np] = BH_OFF +
                sw64((uint32_t)((wn + np * 16 + b_row) * 64 + ks * 32 + b_kof));
    }

    for (int c = 0; c < nch; ++c) {
        CP_WAIT1();
        __syncthreads();
        if (c + 2 < nch)
            load_stage(smb + ((c + 2) % STAGES_) * STAGE_B,
                       Ah, Al, Bh, Bl, row0, col0, (c + 2) * BK_, K, tid);
        CP_COMMIT();

        const uint32_t sb = smb + (c % STAGES_) * STAGE_B;
#pragma unroll
        for (int ks = 0; ks < 2; ++ks) {
            uint32_t fBh[2][4], fBl[2][4];
#pragma unroll
            for (int np = 0; np < 2; ++np) {
                LDSM4(fBh[np], sb + offB[ks][np]);
                LDSM4(fBl[np], sb + offB[ks][np] + (BL_OFF - BH_OFF));
            }
#pragma unroll
            for (int mt = 0; mt < 4; ++mt) {
                uint32_t fAh[4], fAl[4];
                LDSM4(fAh, sb + offA[ks][mt]);
                LDSM4(fAl, sb + offA[ks][mt] + (AL_OFF - AH_OFF));
                // product-major order: dependent MMAs into the same acc are
                // 4 instructions apart instead of back-to-back
#pragma unroll
                for (int nt = 0; nt < 4; ++nt) {
                    const int np = nt >> 1, rr = (nt & 1) * 2;
                    MMA_BF16(acc[mt][nt], fAh, fBh[np][rr], fBh[np][rr + 1]);
                }
#pragma unroll
                for (int nt = 0; nt < 4; ++nt) {
                    const int np = nt >> 1, rr = (nt & 1) * 2;
                    MMA_BF16(acc[mt][nt], fAh, fBl[np][rr], fBl[np][rr + 1]);
                }
#pragma unroll
                for (int nt = 0; nt < 4; ++nt) {
                    const int np = nt >> 1, rr = (nt & 1) * 2;
                    MMA_BF16(acc[mt][nt], fAl, fBh[np][rr], fBh[np][rr + 1]);
                }
            }
        }
    }

    // epilogue: direct float2 stores
#pragma unroll
    for (int mt = 0; mt < 4; ++mt) {
        const int r0 = row0 + wm + mt * 16 + (lane >> 2);
#pragma unroll
        for (int nt = 0; nt < 4; ++nt) {
            const int cc = col0 + wn + nt * 8 + (lane & 3) * 2;
            float v0 = acc[mt][nt][0], v1 = acc[mt][nt][1];
            float v2 = acc[mt][nt][2], v3 = acc[mt][nt][3];
            if (MODE == 1) {
                const float b0 = __ldg(&bias[cc]), b1 = __ldg(&bias[cc + 1]);
                v0 = softplus_f(v0 + b0); v1 = softplus_f(v1 + b1);
                v2 = softplus_f(v2 + b0); v3 = softplus_f(v3 + b1);
            }
            *(float2*)&C[(size_t)r0 * N + cc]       = make_float2(v0, v1);
            *(float2*)&C[(size_t)(r0 + 8) * N + cc] = make_float2(v2, v3);
        }
    }
}

// ---------------- fused hi/lo bf16 split of all four fp32 sources ----------
#define N0_ (M_ * DIM_)            // x
#define N1_ (2 * DIN_ * DIM_)      // W_in
#define N2_ (DIN_ * DIN_)          // dt_w
#define N3_ (DIM_ * DIN_)          // W_out
#define NSPLIT4_ ((N0_ + N1_ + N2_ + N3_) / 4)

__device__ __forceinline__ void split4_store(const float4 v, bf16* hi, bf16* lo, int i4)
{
    bf16 h0, l0, h1, l1, h2, l2, h3, l3;
    split_bf16(v.x, h0, l0); split_bf16(v.y, h1, l1);
    split_bf16(v.z, h2, l2); split_bf16(v.w, h3, l3);
    ushort4 hv = make_ushort4(__bfloat16_as_ushort(h0), __bfloat16_as_ushort(h1),
                              __bfloat16_as_ushort(h2), __bfloat16_as_ushort(h3));
    ushort4 lv = make_ushort4(__bfloat16_as_ushort(l0), __bfloat16_as_ushort(l1),
                              __bfloat16_as_ushort(l2), __bfloat16_as_ushort(l3));
    *(ushort4*)&hi[i4 * 4] = hv;
    *(ushort4*)&lo[i4 * 4] = lv;
}

__global__ void __launch_bounds__(256)
split_all_kernel(const float* __restrict__ x, const float* __restrict__ W_in,
                 const float* __restrict__ dt_w, const float* __restrict__ W_out)
{
    int i = blockIdx.x * blockDim.x + threadIdx.x;
    if (i >= NSPLIT4_) return;
    if (i < N0_ / 4) {
        split4_store(*(const float4*)&x[i * 4], g_xh, g_xl, i);
    } else if (i < (N0_ + N1_) / 4) {
        int j = i - N0_ / 4;
        split4_store(*(const float4*)&W_in[j * 4], g_wih, g_wil, j);
    } else if (i < (N0_ + N1_ + N2_) / 4) {
        int j = i - (N0_ + N1_) / 4;
        split4_store(*(const float4*)&dt_w[j * 4], g_dwh, g_dwl, j);
    } else {
        int j = i - (N0_ + N1_ + N2_) / 4;
        split4_store(*(const float4*)&W_out[j * 4], g_woh, g_wol, j);
    }
}

// ---------------- depthwise conv3 (pad=1) + bias + SiLU + split -----------
__global__ void __launch_bounds__(256)
conv_silu_kernel(const float* __restrict__ cw, const float* __restrict__ cb)
{
    int idx = blockIdx.x * blockDim.x + threadIdx.x;  // over M_*DIN_
    int c  = idx % DIN_;
    int bl = idx / DIN_;
    int l  = bl % L_;
    const float* base = g_xz + (size_t)bl * (2 * DIN_) + c;
    float x0 = base[0];
    float xm = (l > 0)      ? base[-(2 * DIN_)] : 0.f;
    float xp = (l < L_ - 1) ? base[ (2 * DIN_)] : 0.f;
    float w0 = __ldg(&cw[c * 3 + 0]);
    float w1 = __ldg(&cw[c * 3 + 1]);
    float w2 = __ldg(&cw[c * 3 + 2]);
    float v = fmaf(w0, xm, fmaf(w1, x0, fmaf(w2, xp, __ldg(&cb[c]))));
    v = silu_f(v);
    bf16 h, lo;
    split_bf16(v, h, lo);
    g_xch[idx] = h;
    g_xcl[idx] = lo;
}

// ---------------- scan phase 1: per-chunk sums only (ae/s recomputed) -----
__global__ void __launch_bounds__(256)
scan_phase1(const float* __restrict__ Aw)
{
    const int ct = blockIdx.y % (DIN_ / 256);
    const int b  = blockIdx.y / (DIN_ / 256);
    const int ch = blockIdx.x;
    const int c  = ct * 256 + threadIdx.x;
    const float Ac = __ldg(&Aw[c]);
    size_t base = ((size_t)b * L_ + (size_t)ch * CHUNK_) * DIN_ + c;
    float sum = 0.f;
#pragma unroll 4
    for (int i = 0; i < CHUNK_; i++) {
        size_t off = base + (size_t)i * DIN_;
        float dt = g_dt[off];
        float xc = __bfloat162float(g_xch[off]) + __bfloat162float(g_xcl[off]);
        sum += xc * dt * expf(Ac * dt);
    }
    g_csum[((size_t)b * NCHUNK_ + ch) * DIN_ + c] = sum;
}

// ---------------- scan phase 2: exclusive prefix over chunks --------------
__global__ void __launch_bounds__(256)
scan_phase2()
{
    int idx = blockIdx.x * blockDim.x + threadIdx.x;  // over B_*DIN_
    int c = idx % DIN_;
    int b = idx / DIN_;
    float run = 0.f;
    for (int ch = 0; ch < NCHUNK_; ch++) {
        size_t o = ((size_t)b * NCHUNK_ + ch) * DIN_ + c;
        float v = g_csum[o];
        g_cpre[o] = run;
        run += v;
    }
}

// ---------------- scan phase 3: recompute ae/s, gate, split ---------------
__global__ void __launch_bounds__(256)
scan_phase3(const float* __restrict__ Aw, const float* __restrict__ Dp)
{
    const int ct = blockIdx.y % (DIN_ / 256);
    const int b  = blockIdx.y / (DIN_ / 256);
    const int ch = blockIdx.x;
    const int c  = ct * 256 + threadIdx.x;
    const float Ac = __ldg(&Aw[c]);
    const float Dc = __ldg(&Dp[c]);
    float run = g_cpre[((size_t)b * NCHUNK_ + ch) * DIN_ + c];
    size_t base  = ((size_t)b * L_ + (size_t)ch * CHUNK_) * DIN_ + c;
    size_t zbase = ((size_t)b * L_ + (size_t)ch * CHUNK_) * (2 * DIN_) + DIN_ + c;
#pragma unroll 4
    for (int i = 0; i < CHUNK_; i++) {
        size_t off = base + (size_t)i * DIN_;
        float dt = g_dt[off];
        float xc = __bfloat162float(g_xch[off]) + __bfloat162float(g_xcl[off]);
        float ae = expf(Ac * dt);   // bit-identical to phase 1's value
        run += xc * dt * ae;
        float y  = run * ae + xc * Dc;
        float z  = g_xz[zbase + (size_t)i * (2 * DIN_)];
        y *= silu_f(z);
        bf16 h, lo;
        split_bf16(y, h, lo);
        g_yh[off] = h;
        g_yl[off] = lo;
    }
}

// ---------------------------------------------------------------------------
extern "C" void kernel_launch(void* const* d_in, const int* in_sizes, int n_in,
                              void* d_out, int out_size)
{
    const float* x      = (const float*)d_in[0];
    const float* W_in   = (const float*)d_in[1];
    const float* W_out  = (const float*)d_in[2];
    const float* conv_w = (const float*)d_in[3];
    const float* conv_b = (const float*)d_in[4];
    const float* dt_w   = (const float*)d_in[5];
    const float* dt_b   = (const float*)d_in[6];
    const float* Aw     = (const float*)d_in[7];
    const float* Dp     = (const float*)d_in[8];
    float* out = (float*)d_out;

    float *p_xz, *p_dt;
    bf16 *p_xh, *p_xl, *p_wih, *p_wil, *p_dwh, *p_dwl, *p_woh, *p_wol;
    bf16 *p_xch, *p_xcl, *p_yh, *p_yl;
    cudaGetSymbolAddress((void**)&p_xz, g_xz);
    cudaGetSymbolAddress((void**)&p_dt, g_dt);
    cudaGetSymbolAddress((void**)&p_xh, g_xh);
    cudaGetSymbolAddress((void**)&p_xl, g_xl);
    cudaGetSymbolAddress((void**)&p_wih, g_wih);
    cudaGetSymbolAddress((void**)&p_wil, g_wil);
    cudaGetSymbolAddress((void**)&p_dwh, g_dwh);
    cudaGetSymbolAddress((void**)&p_dwl, g_dwl);
    cudaGetSymbolAddress((void**)&p_woh, g_woh);
    cudaGetSymbolAddress((void**)&p_wol, g_wol);
    cudaGetSymbolAddress((void**)&p_xch, g_xch);
    cudaGetSymbolAddress((void**)&p_xcl, g_xcl);
    cudaGetSymbolAddress((void**)&p_yh, g_yh);
    cudaGetSymbolAddress((void**)&p_yl, g_yl);

    cudaFuncSetAttribute(bf16_gemm<0>, cudaFuncAttributeMaxDynamicSharedMemorySize, GEMM_SMEM);
    cudaFuncSetAttribute(bf16_gemm<1>, cudaFuncAttributeMaxDynamicSharedMemorySize, GEMM_SMEM);

    // 1) fused bf16 hi/lo splits (x, W_in, dt_w, W_out)
    split_all_kernel<<<(NSPLIT4_ + 255) / 256, 256>>>(x, W_in, dt_w, W_out);

    // 2) in_proj: xz[M,3072] = x @ W_in^T   (3x-bf16 mma)
    bf16_gemm<0><<<dim3((2 * DIN_) / 128, M_ / 128), 256, GEMM_SMEM>>>(
        p_xh, p_xl, p_wih, p_wil, p_xz, nullptr, M_, 2 * DIN_, DIM_);

    // 3) depthwise conv3 + bias + SiLU (+ split)
    conv_silu_kernel<<<(M_ * DIN_) / 256, 256>>>(conv_w, conv_b);

    // 4) dt = softplus(x_conv @ dt_w^T + dt_b)  <- launch slot 4: ncu target
    bf16_gemm<1><<<dim3(DIN_ / 128, M_ / 128), 256, GEMM_SMEM>>>(
        p_xch, p_xcl, p_dwh, p_dwl, p_dt, dt_b, M_, DIN_, DIN_);

    // 5) chunked cumsum scan + gating (y written as bf16 hi/lo)
    scan_phase1<<<dim3(NCHUNK_, B_ * (DIN_ / 256)), 256>>>(Aw);
    scan_phase2<<<(B_ * DIN_) / 256, 256>>>();
    scan_phase3<<<dim3(NCHUNK_, B_ * (DIN_ / 256)), 256>>>(Aw, Dp);

    // 6) out_proj: out[M,1024] = y @ W_out^T
    bf16_gemm<0><<<dim3(DIM_ / 128, M_ / 128), 256, GEMM_SMEM>>>(
        p_yh, p_yl, p_woh, p_wol, out, nullptr, M_, DIM_, DIN_);
}

// round 13
// speedup vs baseline: 3.3028x; 1.0756x over previous
#include <cuda_runtime.h>
#include <cuda_bf16.h>
#include <math.h>
#include <stdint.h>

#define DIM_  1024
#define DIN_  1536
#define B_    4
#define L_    4096
#define M_    (B_ * L_)          // 16384
#define NCHUNK_ 32
#define CHUNK_  (L_ / NCHUNK_)   // 128

typedef __nv_bfloat16 bf16;

// ---------------- static scratch (no allocations allowed) ----------------
__device__ __align__(16) float g_xz[(size_t)M_ * 2 * DIN_];   // in_proj out [M,3072]
__device__ __align__(16) bf16  g_xch[(size_t)M_ * DIN_];      // silu(conv) hi
__device__ __align__(16) bf16  g_xcl[(size_t)M_ * DIN_];      // silu(conv) lo
__device__ __align__(16) float g_dt[(size_t)M_ * DIN_];
__device__ __align__(16) bf16  g_yh[(size_t)M_ * DIN_];
__device__ __align__(16) bf16  g_yl[(size_t)M_ * DIN_];
__device__ __align__(16) bf16  g_xh[(size_t)M_ * DIM_];
__device__ __align__(16) bf16  g_xl[(size_t)M_ * DIM_];
__device__ __align__(16) bf16  g_wih[(size_t)2 * DIN_ * DIM_];
__device__ __align__(16) bf16  g_wil[(size_t)2 * DIN_ * DIM_];
__device__ __align__(16) bf16  g_dwh[(size_t)DIN_ * DIN_];
__device__ __align__(16) bf16  g_dwl[(size_t)DIN_ * DIN_];
__device__ __align__(16) bf16  g_woh[(size_t)DIM_ * DIN_];
__device__ __align__(16) bf16  g_wol[(size_t)DIM_ * DIN_];
__device__ float g_csum[B_ * NCHUNK_ * DIN_];
__device__ float g_cpre[B_ * NCHUNK_ * DIN_];

__device__ __forceinline__ float softplus_f(float v) {
    return v > 20.f ? v : log1pf(expf(v));
}
__device__ __forceinline__ float silu_f(float v) {
    return v / (1.f + expf(-v));
}
__device__ __forceinline__ void split_bf16(float v, bf16& h, bf16& l) {
    h = __float2bfloat16_rn(v);
    l = __float2bfloat16_rn(v - __bfloat162float(h));
}

// ======================= PTX helpers (base sm_90+/sm_103, no 'a' features) ===
__device__ __forceinline__ uint32_t smem_u32(const void* p) {
    uint32_t a;
    asm("{ .reg .u64 t; cvta.to.shared.u64 t, %1; cvt.u32.u64 %0, t; }" : "=r"(a) : "l"(p));
    return a;
}
#define CP16(saddr, gptr) \
    asm volatile("cp.async.cg.shared.global [%0], [%1], 16;" :: "r"(saddr), "l"(gptr))

#define MBAR_INIT(addr, cnt) \
    asm volatile("mbarrier.init.shared.b64 [%0], %1;" :: "r"(addr), "r"(cnt) : "memory")
#define MBAR_ARRIVE(addr) \
    asm volatile("mbarrier.arrive.shared.b64 _, [%0];" :: "r"(addr) : "memory")
// arrive on mbar when all of this thread's prior cp.asyncs have completed
#define CPA_ARRIVE(addr) \
    asm volatile("cp.async.mbarrier.arrive.noinc.shared.b64 [%0];" :: "r"(addr) : "memory")
#define MBAR_WAIT(addr, ph) do {                                                   \
    uint32_t _m = (addr); uint32_t _p = (ph); uint32_t _d;                         \
    asm volatile("{ .reg .pred p; mbarrier.try_wait.parity.acquire.cta.shared::cta.b64 p, [%1], %2; selp.b32 %0,1,0,p; }" \
        : "=r"(_d) : "r"(_m), "r"(_p) : "memory");                                 \
    if (!_d) {                                                                     \
        asm volatile("{ .reg .pred P1; WL%=: mbarrier.try_wait.parity.acquire.cta.shared::cta.b64 P1, [%0], %1, 0x989680; @P1 bra.uni WD%=; bra.uni WL%=; WD%=: }" \
            :: "r"(_m), "r"(_p) : "memory");                                       \
    } } while (0)

#define LDSM4(r, a) \
    asm volatile("ldmatrix.sync.aligned.m8n8.x4.shared.b16 {%0,%1,%2,%3}, [%4];" \
        : "=r"((r)[0]), "=r"((r)[1]), "=r"((r)[2]), "=r"((r)[3]) : "r"(a))

#define MMA_BF16(d, a, b0v, b1v) \
    asm volatile("mma.sync.aligned.m16n8k16.row.col.f32.bf16.bf16.f32 " \
        "{%0,%1,%2,%3}, {%4,%5,%6,%7}, {%8,%9}, {%0,%1,%2,%3};" \
        : "+f"((d)[0]), "+f"((d)[1]), "+f"((d)[2]), "+f"((d)[3]) \
        : "r"((a)[0]), "r"((a)[1]), "r"((a)[2]), "r"((a)[3]), "r"(b0v), "r"(b1v))

__device__ __forceinline__ uint32_t sw64(uint32_t off) {
    return off ^ ((off >> 3) & 0x30);
}

// ======================= 3x-bf16 mma.sync GEMM, mbarrier pipeline ============
// C[m,n] = sum_k (Ah+Al)[m,k] * (Bh+Bl)[n,k], both K-contiguous bf16.
// Block 128x128, BK=32, 256 threads (8 warps: 2 M x 4 N, warp tile 64x32).
// 2-stage ping-pong, per-stage full/empty mbarriers, NO __syncthreads in the
// main loop: warps desynchronize so MMA tails cover other warps' LDSM windows.
#define BK_      32
#define STAGE_B  32768          // Ah 8K | Al 8K | Bh 8K | Bl 8K
#define AH_OFF   0
#define AL_OFF   8192
#define BH_OFF   16384
#define BL_OFF   24576
#define GEMM_SMEM (2 * STAGE_B)

__device__ __forceinline__ void load_stage(
    uint32_t sb, const bf16* __restrict__ Ah, const bf16* __restrict__ Al,
    const bf16* __restrict__ Bh, const bf16* __restrict__ Bl,
    int row0, int col0, int k0, int K, int tid)
{
#pragma unroll
    for (int i = 0; i < 2; ++i) {
        const int idx = tid + i * 256;          // 0..511
        const int r  = idx >> 2;                // 0..127
        const int kg = idx & 3;                 // 16B group along K
        const uint32_t so = sw64((uint32_t)(r * 64 + kg * 16));
        const size_t ga = (size_t)(row0 + r) * K + k0 + kg * 8;
        const size_t gb = (size_t)(col0 + r) * K + k0 + kg * 8;
        CP16(sb + AH_OFF + so, Ah + ga);
        CP16(sb + AL_OFF + so, Al + ga);
        CP16(sb + BH_OFF + so, Bh + gb);
        CP16(sb + BL_OFF + so, Bl + gb);
    }
}

// MODE 0: plain store.  MODE 1: softplus(acc + bias[n]).
template <int MODE>
__global__ void __launch_bounds__(256, 2)
bf16_gemm(const bf16* __restrict__ Ah, const bf16* __restrict__ Al,
          const bf16* __restrict__ Bh, const bf16* __restrict__ Bl,
          float* __restrict__ C, const float* __restrict__ bias,
          int M, int N, int K)
{
    extern __shared__ char smem_raw[];
    __shared__ __align__(8) uint64_t s_mbar[4];   // full0, full1, empty0, empty1
    const uint32_t smb = smem_u32(smem_raw);
    const int tid  = threadIdx.x;
    const int lane = tid & 31;
    const int wid  = tid >> 5;
    const int wm   = (wid >> 2) * 64;   // warp M base within block
    const int wn   = (wid & 3) * 32;    // warp N base within block
    const int row0 = blockIdx.y * 128;
    const int col0 = blockIdx.x * 128;
    const int nch  = K / BK_;           // even for all three GEMMs

    if (tid == 0) {
        MBAR_INIT(smem_u32(&s_mbar[0]), 256);
        MBAR_INIT(smem_u32(&s_mbar[1]), 256);
        MBAR_INIT(smem_u32(&s_mbar[2]), 256);
        MBAR_INIT(smem_u32(&s_mbar[3]), 256);
    }
    __syncthreads();
    const uint32_t mbf0 = smem_u32(&s_mbar[0]);
    const uint32_t mbf1 = smem_u32(&s_mbar[1]);
    const uint32_t mbe0 = smem_u32(&s_mbar[2]);
    const uint32_t mbe1 = smem_u32(&s_mbar[3]);

    float acc[4][4][4];
#pragma unroll
    for (int i = 0; i < 4; ++i)
#pragma unroll
        for (int j = 0; j < 4; ++j)
#pragma unroll
            for (int t = 0; t < 4; ++t) acc[i][j][t] = 0.f;

    // prologue: fill both stages (stages start empty, no wait needed)
    load_stage(smb, Ah, Al, Bh, Bl, row0, col0, 0, K, tid);
    CPA_ARRIVE(mbf0);
    load_stage(smb + STAGE_B, Ah, Al, Bh, Bl, row0, col0, BK_, K, tid);
    CPA_ARRIVE(mbf1);

    // hoisted per-lane ldmatrix tile-local swizzled offsets
    const int a_row = (lane & 7) + ((lane >> 3) & 1) * 8;
    const int a_kof = ((lane >> 4) & 1) * 16;
    const int b_row = (lane & 7) + ((lane >> 4) & 1) * 8;
    const int b_kof = ((lane >> 3) & 1) * 16;
    uint32_t offA[2][4], offB[2][2];
#pragma unroll
    for (int ks = 0; ks < 2; ++ks) {
#pragma unroll
        for (int mt = 0; mt < 4; ++mt)
            offA[ks][mt] = AH_OFF +
                sw64((uint32_t)((wm + mt * 16 + a_row) * 64 + ks * 32 + a_kof));
#pragma unroll
        for (int np = 0; np < 2; ++np)
            offB[ks][np] = BH_OFF +
                sw64((uint32_t)((wn + np * 16 + b_row) * 64 + ks * 32 + b_kof));
    }

    const int T = nch >> 1;
    for (int t = 0; t < T; ++t) {
        const uint32_t par = (uint32_t)(t & 1);
#pragma unroll
        for (int h = 0; h < 2; ++h) {
            const uint32_t sb  = smb + h * STAGE_B;
            const uint32_t mbf = h ? mbf1 : mbf0;
            const uint32_t mbe = h ? mbe1 : mbe0;

            MBAR_WAIT(mbf, par);   // all threads' copies for this stage landed
#pragma unroll
            for (int ks = 0; ks < 2; ++ks) {
                uint32_t fBh[2][4], fBl[2][4];
#pragma unroll
                for (int np = 0; np < 2; ++np) {
                    LDSM4(fBh[np], sb + offB[ks][np]);
                    LDSM4(fBl[np], sb + offB[ks][np] + (BL_OFF - BH_OFF));
                }
#pragma unroll
                for (int mt = 0; mt < 4; ++mt) {
                    uint32_t fAh[4], fAl[4];
                    LDSM4(fAh, sb + offA[ks][mt]);
                    LDSM4(fAl, sb + offA[ks][mt] + (AL_OFF - AH_OFF));
                    // last LDSM of this stage -> signal "stage read complete"
                    if (ks == 1 && mt == 3) MBAR_ARRIVE(mbe);
#pragma unroll
                    for (int nt = 0; nt < 4; ++nt) {
                        const int np = nt >> 1, rr = (nt & 1) * 2;
                        MMA_BF16(acc[mt][nt], fAh, fBh[np][rr], fBh[np][rr + 1]);
                    }
#pragma unroll
                    for (int nt = 0; nt < 4; ++nt) {
                        const int np = nt >> 1, rr = (nt & 1) * 2;
                        MMA_BF16(acc[mt][nt], fAh, fBl[np][rr], fBl[np][rr + 1]);
                    }
#pragma unroll
                    for (int nt = 0; nt < 4; ++nt) {
                        const int np = nt >> 1, rr = (nt & 1) * 2;
                        MMA_BF16(acc[mt][nt], fAl, fBh[np][rr], fBh[np][rr + 1]);
                    }
                }
            }
            if (t < T - 1) {
                // overwrite guard: only waits for all warps' LDSM (cheap),
                // issued after this warp's MMAs so it's usually satisfied
                MBAR_WAIT(mbe, par);
                load_stage(sb, Ah, Al, Bh, Bl, row0, col0,
                           (2 * t + h + 2) * BK_, K, tid);
                CPA_ARRIVE(mbf);
            }
        }
    }

    // epilogue: direct float2 stores
#pragma unroll
    for (int mt = 0; mt < 4; ++mt) {
        const int r0 = row0 + wm + mt * 16 + (lane >> 2);
#pragma unroll
        for (int nt = 0; nt < 4; ++nt) {
            const int cc = col0 + wn + nt * 8 + (lane & 3) * 2;
            float v0 = acc[mt][nt][0], v1 = acc[mt][nt][1];
            float v2 = acc[mt][nt][2], v3 = acc[mt][nt][3];
            if (MODE == 1) {
                const float b0 = __ldg(&bias[cc]), b1 = __ldg(&bias[cc + 1]);
                v0 = softplus_f(v0 + b0); v1 = softplus_f(v1 + b1);
                v2 = softplus_f(v2 + b0); v3 = softplus_f(v3 + b1);
            }
            *(float2*)&C[(size_t)r0 * N + cc]       = make_float2(v0, v1);
            *(float2*)&C[(size_t)(r0 + 8) * N + cc] = make_float2(v2, v3);
        }
    }
}

// ---------------- fused hi/lo bf16 split of all four fp32 sources ----------
#define N0_ (M_ * DIM_)            // x
#define N1_ (2 * DIN_ * DIM_)      // W_in
#define N2_ (DIN_ * DIN_)          // dt_w
#define N3_ (DIM_ * DIN_)          // W_out
#define NSPLIT4_ ((N0_ + N1_ + N2_ + N3_) / 4)

__device__ __forceinline__ void split4_store(const float4 v, bf16* hi, bf16* lo, int i4)
{
    bf16 h0, l0, h1, l1, h2, l2, h3, l3;
    split_bf16(v.x, h0, l0); split_bf16(v.y, h1, l1);
    split_bf16(v.z, h2, l2); split_bf16(v.w, h3, l3);
    ushort4 hv = make_ushort4(__bfloat16_as_ushort(h0), __bfloat16_as_ushort(h1),
                              __bfloat16_as_ushort(h2), __bfloat16_as_ushort(h3));
    ushort4 lv = make_ushort4(__bfloat16_as_ushort(l0), __bfloat16_as_ushort(l1),
                              __bfloat16_as_ushort(l2), __bfloat16_as_ushort(l3));
    *(ushort4*)&hi[i4 * 4] = hv;
    *(ushort4*)&lo[i4 * 4] = lv;
}

__global__ void __launch_bounds__(256)
split_all_kernel(const float* __restrict__ x, const float* __restrict__ W_in,
                 const float* __restrict__ dt_w, const float* __restrict__ W_out)
{
    int i = blockIdx.x * blockDim.x + threadIdx.x;
    if (i >= NSPLIT4_) return;
    if (i < N0_ / 4) {
        split4_store(*(const float4*)&x[i * 4], g_xh, g_xl, i);
    } else if (i < (N0_ + N1_) / 4) {
        int j = i - N0_ / 4;
        split4_store(*(const float4*)&W_in[j * 4], g_wih, g_wil, j);
    } else if (i < (N0_ + N1_ + N2_) / 4) {
        int j = i - (N0_ + N1_) / 4;
        split4_store(*(const float4*)&dt_w[j * 4], g_dwh, g_dwl, j);
    } else {
        int j = i - (N0_ + N1_ + N2_) / 4;
        split4_store(*(const float4*)&W_out[j * 4], g_woh, g_wol, j);
    }
}

// ---------------- depthwise conv3 (pad=1) + bias + SiLU + split -----------
__global__ void __launch_bounds__(256)
conv_silu_kernel(const float* __restrict__ cw, const float* __restrict__ cb)
{
    int idx = blockIdx.x * blockDim.x + threadIdx.x;  // over M_*DIN_
    int c  = idx % DIN_;
    int bl = idx / DIN_;
    int l  = bl % L_;
    const float* base = g_xz + (size_t)bl * (2 * DIN_) + c;
    float x0 = base[0];
    float xm = (l > 0)      ? base[-(2 * DIN_)] : 0.f;
    float xp = (l < L_ - 1) ? base[ (2 * DIN_)] : 0.f;
    float w0 = __ldg(&cw[c * 3 + 0]);
    float w1 = __ldg(&cw[c * 3 + 1]);
    float w2 = __ldg(&cw[c * 3 + 2]);
    float v = fmaf(w0, xm, fmaf(w1, x0, fmaf(w2, xp, __ldg(&cb[c]))));
    v = silu_f(v);
    bf16 h, lo;
    split_bf16(v, h, lo);
    g_xch[idx] = h;
    g_xcl[idx] = lo;
}

// ---------------- scan phase 1: per-chunk sums only (ae/s recomputed) -----
__global__ void __launch_bounds__(256)
scan_phase1(const float* __restrict__ Aw)
{
    const int ct = blockIdx.y % (DIN_ / 256);
    const int b  = blockIdx.y / (DIN_ / 256);
    const int ch = blockIdx.x;
    const int c  = ct * 256 + threadIdx.x;
    const float Ac = __ldg(&Aw[c]);
    size_t base = ((size_t)b * L_ + (size_t)ch * CHUNK_) * DIN_ + c;
    float sum = 0.f;
#pragma unroll 4
    for (int i = 0; i < CHUNK_; i++) {
        size_t off = base + (size_t)i * DIN_;
        float dt = g_dt[off];
        float xc = __bfloat162float(g_xch[off]) + __bfloat162float(g_xcl[off]);
        sum += xc * dt * expf(Ac * dt);
    }
    g_csum[((size_t)b * NCHUNK_ + ch) * DIN_ + c] = sum;
}

// ---------------- scan phase 2: exclusive prefix over chunks --------------
__global__ void __launch_bounds__(256)
scan_phase2()
{
    int idx = blockIdx.x * blockDim.x + threadIdx.x;  // over B_*DIN_
    int c = idx % DIN_;
    int b = idx / DIN_;
    float run = 0.f;
    for (int ch = 0; ch < NCHUNK_; ch++) {
        size_t o = ((size_t)b * NCHUNK_ + ch) * DIN_ + c;
        float v = g_csum[o];
        g_cpre[o] = run;
        run += v;
    }
}

// ---------------- scan phase 3: recompute ae/s, gate, split ---------------
__global__ void __launch_bounds__(256)
scan_phase3(const float* __restrict__ Aw, const float* __restrict__ Dp)
{
    const int ct = blockIdx.y % (DIN_ / 256);
    const int b  = blockIdx.y / (DIN_ / 256);
    const int ch = blockIdx.x;
    const int c  = ct * 256 + threadIdx.x;
    const float Ac = __ldg(&Aw[c]);
    const float Dc = __ldg(&Dp[c]);
    float run = g_cpre[((size_t)b * NCHUNK_ + ch) * DIN_ + c];
    size_t base  = ((size_t)b * L_ + (size_t)ch * CHUNK_) * DIN_ + c;
    size_t zbase = ((size_t)b * L_ + (size_t)ch * CHUNK_) * (2 * DIN_) + DIN_ + c;
#pragma unroll 4
    for (int i = 0; i < CHUNK_; i++) {
        size_t off = base + (size_t)i * DIN_;
        float dt = g_dt[off];
        float xc = __bfloat162float(g_xch[off]) + __bfloat162float(g_xcl[off]);
        float ae = expf(Ac * dt);   // bit-identical to phase 1's value
        run += xc * dt * ae;
        float y  = run * ae + xc * Dc;
        float z  = g_xz[zbase + (size_t)i * (2 * DIN_)];
        y *= silu_f(z);
        bf16 h, lo;
        split_bf16(y, h, lo);
        g_yh[off] = h;
        g_yl[off] = lo;
    }
}

// ---------------------------------------------------------------------------
extern "C" void kernel_launch(void* const* d_in, const int* in_sizes, int n_in,
                              void* d_out, int out_size)
{
    const float* x      = (const float*)d_in[0];
    const float* W_in   = (const float*)d_in[1];
    const float* W_out  = (const float*)d_in[2];
    const float* conv_w = (const float*)d_in[3];
    const float* conv_b = (const float*)d_in[4];
    const float* dt_w   = (const float*)d_in[5];
    const float* dt_b   = (const float*)d_in[6];
    const float* Aw     = (const float*)d_in[7];
    const float* Dp     = (const float*)d_in[8];
    float* out = (float*)d_out;

    float *p_xz, *p_dt;
    bf16 *p_xh, *p_xl, *p_wih, *p_wil, *p_dwh, *p_dwl, *p_woh, *p_wol;
    bf16 *p_xch, *p_xcl, *p_yh, *p_yl;
    cudaGetSymbolAddress((void**)&p_xz, g_xz);
    cudaGetSymbolAddress((void**)&p_dt, g_dt);
    cudaGetSymbolAddress((void**)&p_xh, g_xh);
    cudaGetSymbolAddress((void**)&p_xl, g_xl);
    cudaGetSymbolAddress((void**)&p_wih, g_wih);
    cudaGetSymbolAddress((void**)&p_wil, g_wil);
    cudaGetSymbolAddress((void**)&p_dwh, g_dwh);
    cudaGetSymbolAddress((void**)&p_dwl, g_dwl);
    cudaGetSymbolAddress((void**)&p_woh, g_woh);
    cudaGetSymbolAddress((void**)&p_wol, g_wol);
    cudaGetSymbolAddress((void**)&p_xch, g_xch);
    cudaGetSymbolAddress((void**)&p_xcl, g_xcl);
    cudaGetSymbolAddress((void**)&p_yh, g_yh);
    cudaGetSymbolAddress((void**)&p_yl, g_yl);

    cudaFuncSetAttribute(bf16_gemm<0>, cudaFuncAttributeMaxDynamicSharedMemorySize, GEMM_SMEM);
    cudaFuncSetAttribute(bf16_gemm<1>, cudaFuncAttributeMaxDynamicSharedMemorySize, GEMM_SMEM);

    // 1) fused bf16 hi/lo splits (x, W_in, dt_w, W_out)
    split_all_kernel<<<(NSPLIT4_ + 255) / 256, 256>>>(x, W_in, dt_w, W_out);

    // 2) in_proj: xz[M,3072] = x @ W_in^T   (3x-bf16 mma)
    bf16_gemm<0><<<dim3((2 * DIN_) / 128, M_ / 128), 256, GEMM_SMEM>>>(
        p_xh, p_xl, p_wih, p_wil, p_xz, nullptr, M_, 2 * DIN_, DIM_);

    // 3) depthwise conv3 + bias + SiLU (+ split)
    conv_silu_kernel<<<(M_ * DIN_) / 256, 256>>>(conv_w, conv_b);

    // 4) dt = softplus(x_conv @ dt_w^T + dt_b)  <- launch slot 4: ncu target
    bf16_gemm<1><<<dim3(DIN_ / 128, M_ / 128), 256, GEMM_SMEM>>>(
        p_xch, p_xcl, p_dwh, p_dwl, p_dt, dt_b, M_, DIN_, DIN_);

    // 5) chunked cumsum scan + gating (y written as bf16 hi/lo)
    scan_phase1<<<dim3(NCHUNK_, B_ * (DIN_ / 256)), 256>>>(Aw);
    scan_phase2<<<(B_ * DIN_) / 256, 256>>>();
    scan_phase3<<<dim3(NCHUNK_, B_ * (DIN_ / 256)), 256>>>(Aw, Dp);

    // 6) out_proj: out[M,1024] = y @ W_out^T
    bf16_gemm<0><<<dim3(DIM_ / 128, M_ / 128), 256, GEMM_SMEM>>>(
        p_yh, p_yl, p_woh, p_wol, out, nullptr, M_, DIM_, DIN_);
}